// round 1
// baseline (speedup 1.0000x reference)
#include <cuda_runtime.h>
#include <cuda_bf16.h>
#include <math.h>

#define IMG_H 4096
#define IMG_W 4096
#define TDIM 32          // output tile 32x32
#define NTHREADS 256

// shared tile dims
#define SI 40            // img tile:   (TDIM+8) x (TDIM+8)
#define ST 36            // h-blur out: SI rows x (TDIM+4) cols
#define SB 36            // blur:       (TDIM+4) x (TDIM+4)
#define SM 34            // mag/gx/gy:  (TDIM+2) x (TDIM+2)

__global__ __launch_bounds__(NTHREADS) void canny_fused_kernel(
    const float* __restrict__ img,
    const float* __restrict__ gauss,
    float* __restrict__ out)
{
    __shared__ float s_img[SI * SI];
    __shared__ float s_tmp[SI * ST];   // 40 rows x 36 cols (h-blurred)
    __shared__ float s_blur[SB * SB];
    __shared__ float s_mag[SM * SM];
    __shared__ float s_gx[SM * SM];
    __shared__ float s_gy[SM * SM];

    const int tid = threadIdx.x;
    const int bx = blockIdx.x * TDIM;
    const int by = blockIdx.y * TDIM;

    const float g0 = gauss[0];
    const float g1 = gauss[1];
    const float g2 = gauss[2];
    const float g3 = gauss[3];
    const float g4 = gauss[4];

    // zero accumulators (visible after the syncthreads inside the channel loop)
    for (int i = tid; i < SM * SM; i += NTHREADS) {
        s_mag[i] = 0.0f;
        s_gx[i]  = 0.0f;
        s_gy[i]  = 0.0f;
    }

    for (int c = 0; c < 3; c++) {
        const float* im = img + (size_t)c * IMG_H * IMG_W;

        // ---- stage 1: load 40x40 img tile (zero OOB) ----
        for (int i = tid; i < SI * SI; i += NTHREADS) {
            int y = i / SI, x = i - y * SI;
            int gy_ = by - 4 + y;
            int gx_ = bx - 4 + x;
            float v = 0.0f;
            if (gy_ >= 0 && gy_ < IMG_H && gx_ >= 0 && gx_ < IMG_W)
                v = im[(size_t)gy_ * IMG_W + gx_];
            s_img[i] = v;
        }
        __syncthreads();

        // ---- stage 2: horizontal gaussian: 40 rows x 36 cols ----
        for (int i = tid; i < SI * ST; i += NTHREADS) {
            int y = i / ST, x = i - y * ST;
            const float* r = s_img + y * SI + x;
            s_tmp[i] = g0 * r[0] + g1 * r[1] + g2 * r[2] + g3 * r[3] + g4 * r[4];
        }
        __syncthreads();

        // ---- stage 3: vertical gaussian: 36x36; zero outside image ----
        for (int i = tid; i < SB * SB; i += NTHREADS) {
            int y = i / SB, x = i - y * SB;
            const float* col = s_tmp + y * ST + x;
            float v = g0 * col[0] + g1 * col[ST] + g2 * col[2 * ST]
                    + g3 * col[3 * ST] + g4 * col[4 * ST];
            int gy_ = by - 2 + y;
            int gx_ = bx - 2 + x;
            if (gy_ < 0 || gy_ >= IMG_H || gx_ < 0 || gx_ >= IMG_W) v = 0.0f;
            s_blur[i] = v;
        }
        __syncthreads();

        // ---- stage 4: sobel + accumulate on 34x34 (zero outside image) ----
        for (int i = tid; i < SM * SM; i += NTHREADS) {
            int y = i / SM, x = i - y * SM;
            int gy_ = by - 1 + y;
            int gx_ = bx - 1 + x;
            if (gy_ >= 0 && gy_ < IMG_H && gx_ >= 0 && gx_ < IMG_W) {
                const float* b = s_blur + y * SB + x;
                float b00 = b[0],          b01 = b[1],          b02 = b[2];
                float b10 = b[SB],                               b12 = b[SB + 2];
                float b20 = b[2 * SB],     b21 = b[2 * SB + 1], b22 = b[2 * SB + 2];
                // sobel (cross-correlation): w = [[1,0,-1],[2,0,-2],[1,0,-1]]
                float gxv = (b00 - b02) + 2.0f * (b10 - b12) + (b20 - b22);
                // w^T = [[1,2,1],[0,0,0],[-1,-2,-1]]
                float gyv = (b00 - b20) + 2.0f * (b01 - b21) + (b02 - b22);
                s_mag[i] += sqrtf(gxv * gxv + gyv * gyv + 1e-8f);
                s_gx[i]  += gxv;
                s_gy[i]  += gyv;
            }
        }
        __syncthreads();
    }

    // ---- stage 5: orientation, NMS, threshold, write ----
    // dir k -> the (-1) tap offset relative to center (cross-correlation):
    //   dy8 = {0,1,1,1,0,-1,-1,-1}, dx8 = {1,1,0,-1,-1,-1,0,1}
    // packed as nibbles of (v+1):
    const unsigned DYP = 0x00012221u;  // nibble ip -> dy+1
    const unsigned DXP = 0x21000122u;  // nibble ip -> dx+1
    const float RAD2DEG = (float)(180.0 / 3.14159);

    for (int i = tid; i < TDIM * TDIM; i += NTHREADS) {
        int y = i / TDIM, x = i - y * TDIM;
        int cy = y + 1, cx = x + 1;
        float m   = s_mag[cy * SM + cx];
        float gxv = s_gx[cy * SM + cx];
        float gyv = s_gy[cy * SM + cx];

        float t = atan2f(gyv, gxv) * RAD2DEG + 180.0f;
        int k = (int)rintf(t / 45.0f);   // round-half-even, matches jnp.round; k in [0,8]
        int ip = k & 7;
        int dy = (int)((DYP >> (ip * 4)) & 7u) - 1;
        int dx = (int)((DXP >> (ip * 4)) & 7u) - 1;

        float mp = s_mag[(cy + dy) * SM + (cx + dx)];
        float mn = s_mag[(cy - dy) * SM + (cx - dx)];
        float cs_pos = m - mp;
        float cs_neg = m - mn;

        bool is_max = fminf(cs_pos, cs_neg) > 0.0f;
        float o = (is_max && m >= 6.0f && m <= 50.0f) ? 1.0f : 0.0f;
        out[(size_t)(by + y) * IMG_W + (bx + x)] = o;
    }
}

extern "C" void kernel_launch(void* const* d_in, const int* in_sizes, int n_in,
                              void* d_out, int out_size) {
    const float* img   = (const float*)d_in[0];  // [1,3,4096,4096]
    const float* gauss = (const float*)d_in[1];  // [5]
    // d_in[2] = sobel (hardcoded), d_in[3] = dir_w (hardcoded as offsets)
    float* out = (float*)d_out;                  // [1,1,4096,4096]

    dim3 grid(IMG_W / TDIM, IMG_H / TDIM);
    canny_fused_kernel<<<grid, NTHREADS>>>(img, gauss, out);
}

// round 2
// speedup vs baseline: 1.0947x; 1.0947x over previous
#include <cuda_runtime.h>
#include <math.h>

#define IMG_W 4096
#define IMG_H 4096
#define TW 64           // output tile width
#define TH 32           // output tile height
#define NT 256

// shared buffer strides (floats), all multiples of 4 for LDS.128 alignment
#define SA  76          // bufA: img 40x72 (then aliased: blur 36x68)
#define SBs 68          // bufB: tmp 40x68
#define SMs 72          // bufM: mag rows 1..34, cols jm 0..67

__global__ __launch_bounds__(NT) void canny_kernel(
    const float* __restrict__ img,
    const float* __restrict__ gauss,
    float* __restrict__ out)
{
    __shared__ __align__(16) float bufA[40 * SA];   // img -> blur (aliased)
    __shared__ __align__(16) float bufB[40 * SBs];  // h-blurred tmp
    __shared__ __align__(16) float bufM[36 * SMs];  // channel-summed grad magnitude

    const int tid = threadIdx.x;
    const int bx = blockIdx.x * TW;
    const int by = blockIdx.y * TH;
    // interior: tile + full halo (rows by-4..by+35, cols bx-4..bx+67) inside image
    const bool interior = (blockIdx.x >= 1 && blockIdx.x <= 62 &&
                           blockIdx.y >= 1 && blockIdx.y <= 126);

    const float g0 = gauss[0], g1 = gauss[1], g2 = gauss[2],
                g3 = gauss[3], g4 = gauss[4];

    // this thread's fixed 4-wide x 2-tall output patch
    const int ox = 4 * (tid & 15);
    const int oy = 2 * (tid >> 4);

    float gxa[8], gya[8];
    #pragma unroll
    for (int i = 0; i < 8; i++) { gxa[i] = 0.0f; gya[i] = 0.0f; }

    for (int c = 0; c < 3; c++) {
        const float* im = img + (size_t)c * (IMG_H * IMG_W);

        // ---- S1: load img tile 40 rows x 72 cols into bufA ----
        if (interior) {
            #pragma unroll
            for (int it = 0; it < 3; it++) {
                int p = tid + it * NT;
                if (p < 720) {                       // 40 rows x 18 float4
                    int r = p / 18;
                    int c4 = (p - r * 18) * 4;
                    float4 v = *(const float4*)(im + (size_t)(by - 4 + r) * IMG_W + (bx - 4) + c4);
                    *(float4*)&bufA[r * SA + c4] = v;
                }
            }
        } else {
            for (int p = tid; p < 2880; p += NT) {   // 40 x 72 scalar, zero OOB
                int r = p / 72;
                int cc = p - r * 72;
                int iy = by - 4 + r, ix = bx - 4 + cc;
                float v = 0.0f;
                if (iy >= 0 && iy < IMG_H && ix >= 0 && ix < IMG_W)
                    v = im[(size_t)iy * IMG_W + ix];
                bufA[r * SA + cc] = v;
            }
        }
        __syncthreads();

        // ---- S2: horizontal gaussian -> bufB (40 rows x 68 cols), 2x4 patches ----
        #pragma unroll
        for (int it = 0; it < 2; it++) {
            int p = tid + it * NT;
            if (p < 340) {                           // 20 row-pairs x 17 col4
                int pr = p / 17;
                int pc = p - pr * 17;
                int r0 = 2 * pr, j0 = 4 * pc;
                #pragma unroll
                for (int rr = 0; rr < 2; rr++) {
                    const float* a = &bufA[(r0 + rr) * SA + j0];
                    float4 lo = *(const float4*)a;
                    float4 hi = *(const float4*)(a + 4);
                    float t0 = g0*lo.x + g1*lo.y + g2*lo.z + g3*lo.w + g4*hi.x;
                    float t1 = g0*lo.y + g1*lo.z + g2*lo.w + g3*hi.x + g4*hi.y;
                    float t2 = g0*lo.z + g1*lo.w + g2*hi.x + g3*hi.y + g4*hi.z;
                    float t3 = g0*lo.w + g1*hi.x + g2*hi.y + g3*hi.z + g4*hi.w;
                    *(float4*)&bufB[(r0 + rr) * SBs + j0] = make_float4(t0, t1, t2, t3);
                }
            }
        }
        __syncthreads();

        // ---- S3: vertical gaussian -> blur in bufA (36 rows x 68 cols), 2x4 patches ----
        #pragma unroll
        for (int it = 0; it < 2; it++) {
            int p = tid + it * NT;
            if (p < 306) {                           // 18 row-pairs x 17 col4
                int pr = p / 17;
                int pc = p - pr * 17;
                int r0 = 2 * pr, j0 = 4 * pc;
                float4 t0 = *(const float4*)&bufB[(r0 + 0) * SBs + j0];
                float4 t1 = *(const float4*)&bufB[(r0 + 1) * SBs + j0];
                float4 t2 = *(const float4*)&bufB[(r0 + 2) * SBs + j0];
                float4 t3 = *(const float4*)&bufB[(r0 + 3) * SBs + j0];
                float4 t4 = *(const float4*)&bufB[(r0 + 4) * SBs + j0];
                float4 t5 = *(const float4*)&bufB[(r0 + 5) * SBs + j0];
                float4 b0, b1;
                b0.x = g0*t0.x + g1*t1.x + g2*t2.x + g3*t3.x + g4*t4.x;
                b0.y = g0*t0.y + g1*t1.y + g2*t2.y + g3*t3.y + g4*t4.y;
                b0.z = g0*t0.z + g1*t1.z + g2*t2.z + g3*t3.z + g4*t4.z;
                b0.w = g0*t0.w + g1*t1.w + g2*t2.w + g3*t3.w + g4*t4.w;
                b1.x = g0*t1.x + g1*t2.x + g2*t3.x + g3*t4.x + g4*t5.x;
                b1.y = g0*t1.y + g1*t2.y + g2*t3.y + g3*t4.y + g4*t5.y;
                b1.z = g0*t1.z + g1*t2.z + g2*t3.z + g3*t4.z + g4*t5.z;
                b1.w = g0*t1.w + g1*t2.w + g2*t3.w + g3*t4.w + g4*t5.w;
                if (!interior) {
                    // zero blur outside image (matches conv zero padding)
                    int iy0 = by - 2 + r0;
                    int ixb = bx - 2 + j0;
                    float* p0 = &b0.x; float* p1 = &b1.x;
                    #pragma unroll
                    for (int cc = 0; cc < 4; cc++) {
                        int ix = ixb + cc;
                        bool okx = (ix >= 0 && ix < IMG_W);
                        if (!(okx && iy0     >= 0 && iy0     < IMG_H)) p0[cc] = 0.0f;
                        if (!(okx && iy0 + 1 >= 0 && iy0 + 1 < IMG_H)) p1[cc] = 0.0f;
                    }
                }
                *(float4*)&bufA[(r0 + 0) * SA + j0] = b0;
                *(float4*)&bufA[(r0 + 1) * SA + j0] = b1;
            }
        }
        __syncthreads();

        // ---- S4: sobel magnitude -> bufM (rows 1..34, jm = magcol-1 in 0..67) ----
        #pragma unroll
        for (int it = 0; it < 2; it++) {
            int p = tid + it * NT;
            if (p < 289) {                           // 17 row-pairs x 17 col4
                int pr = p / 17;
                int pc = p - pr * 17;
                int r0 = 1 + 2 * pr;                 // mag rows r0, r0+1 in [1,34]
                int cb = 4 * pc;                     // blur col base (= magcol-1)
                float rv[4][6];
                #pragma unroll
                for (int rr = 0; rr < 4; rr++) {
                    const float* b = &bufA[(r0 - 1 + rr) * SA + cb];
                    float4 lo = *(const float4*)b;
                    float2 hi = *(const float2*)(b + 4);
                    rv[rr][0] = lo.x; rv[rr][1] = lo.y; rv[rr][2] = lo.z;
                    rv[rr][3] = lo.w; rv[rr][4] = hi.x; rv[rr][5] = hi.y;
                }
                #pragma unroll
                for (int rr = 0; rr < 2; rr++) {
                    float mv[4];
                    #pragma unroll
                    for (int cc = 0; cc < 4; cc++) {
                        float b00 = rv[rr][cc],     b01 = rv[rr][cc+1],     b02 = rv[rr][cc+2];
                        float b10 = rv[rr+1][cc],                           b12 = rv[rr+1][cc+2];
                        float b20 = rv[rr+2][cc],   b21 = rv[rr+2][cc+1],   b22 = rv[rr+2][cc+2];
                        float gxv = (b00 - b02) + 2.0f * (b10 - b12) + (b20 - b22);
                        float gyv = (b00 - b20) + 2.0f * (b01 - b21) + (b02 - b22);
                        float m = sqrtf(gxv * gxv + gyv * gyv + 1e-8f);
                        if (!interior) {
                            int iy = by - 2 + r0 + rr;
                            int ix = bx - 2 + cb + 1 + cc;
                            if (iy < 0 || iy >= IMG_H || ix < 0 || ix >= IMG_W) m = 0.0f;
                        }
                        mv[cc] = m;
                    }
                    float* dst = &bufM[(r0 + rr) * SMs + cb];
                    if (c == 0) {
                        *(float4*)dst = make_float4(mv[0], mv[1], mv[2], mv[3]);
                    } else {
                        float4 o = *(const float4*)dst;
                        *(float4*)dst = make_float4(o.x + mv[0], o.y + mv[1],
                                                    o.z + mv[2], o.w + mv[3]);
                    }
                }
            }
        }

        // ---- S4b: sobel gx/gy accumulated in registers at this thread's outputs ----
        {
            float rv[4][8];
            #pragma unroll
            for (int rr = 0; rr < 4; rr++) {
                const float* b = &bufA[(oy + 1 + rr) * SA + ox];
                float4 lo = *(const float4*)b;
                float4 hi = *(const float4*)(b + 4);
                rv[rr][0] = lo.x; rv[rr][1] = lo.y; rv[rr][2] = lo.z; rv[rr][3] = lo.w;
                rv[rr][4] = hi.x; rv[rr][5] = hi.y; rv[rr][6] = hi.z; rv[rr][7] = hi.w;
            }
            #pragma unroll
            for (int rr = 0; rr < 2; rr++) {
                #pragma unroll
                for (int cc = 0; cc < 4; cc++) {
                    float b00 = rv[rr][cc+1],   b01 = rv[rr][cc+2],   b02 = rv[rr][cc+3];
                    float b10 = rv[rr+1][cc+1],                       b12 = rv[rr+1][cc+3];
                    float b20 = rv[rr+2][cc+1], b21 = rv[rr+2][cc+2], b22 = rv[rr+2][cc+3];
                    gxa[rr*4+cc] += (b00 - b02) + 2.0f * (b10 - b12) + (b20 - b22);
                    gya[rr*4+cc] += (b00 - b20) + 2.0f * (b01 - b21) + (b02 - b22);
                }
            }
        }
        __syncthreads();   // mag done / bufA free for next channel
    }

    // ---- S5: orientation, NMS, threshold, write ----
    const unsigned DYP = 0x00012221u;   // nibble ip -> dy+1
    const unsigned DXP = 0x21000122u;   // nibble ip -> dx+1
    const float RAD2DEG = (float)(180.0 / 3.14159);

    #pragma unroll
    for (int rr = 0; rr < 2; rr++) {
        float ov[4];
        #pragma unroll
        for (int cc = 0; cc < 4; cc++) {
            int y = oy + rr, x = ox + cc;
            float m  = bufM[(y + 2) * SMs + (x + 1)];
            float gx = gxa[rr*4+cc];
            float gy = gya[rr*4+cc];
            float t = atan2f(gy, gx) * RAD2DEG + 180.0f;
            int k = (int)rintf(t / 45.0f);
            int ip = k & 7;
            int dy = (int)((DYP >> (ip * 4)) & 7u) - 1;
            int dx = (int)((DXP >> (ip * 4)) & 7u) - 1;
            float mp = bufM[(y + 2 + dy) * SMs + (x + 1 + dx)];
            float mn = bufM[(y + 2 - dy) * SMs + (x + 1 - dx)];
            bool is_max = fminf(m - mp, m - mn) > 0.0f;
            ov[cc] = (is_max && m >= 6.0f && m <= 50.0f) ? 1.0f : 0.0f;
        }
        *(float4*)(out + (size_t)(by + oy + rr) * IMG_W + bx + ox) =
            make_float4(ov[0], ov[1], ov[2], ov[3]);
    }
}

extern "C" void kernel_launch(void* const* d_in, const int* in_sizes, int n_in,
                              void* d_out, int out_size) {
    const float* img   = (const float*)d_in[0];  // [1,3,4096,4096]
    const float* gauss = (const float*)d_in[1];  // [5]
    float* out = (float*)d_out;                  // [1,1,4096,4096]

    dim3 grid(IMG_W / TW, IMG_H / TH);
    canny_kernel<<<grid, NT>>>(img, gauss, out);
}

// round 3
// speedup vs baseline: 1.4849x; 1.3564x over previous
#include <cuda_runtime.h>
#include <math.h>

#define IMG_W 4096
#define IMG_H 4096
#define TW 64           // output tile width
#define TH 32           // output tile height
#define NT 256

// shared buffer strides (floats), all multiples of 4 for LDS.128 alignment
#define SA  76          // bufA: img 40x72 (then aliased: blur 36x68)
#define SBs 68          // bufB: tmp 40x68
#define SMs 72          // bufM: mag rows 1..34, cols jm 0..67

__global__ __launch_bounds__(NT, 4) void canny_kernel(
    const float* __restrict__ img,
    const float* __restrict__ gauss,
    float* __restrict__ out)
{
    __shared__ __align__(16) float bufA[40 * SA];   // img -> blur (aliased)
    __shared__ __align__(16) float bufB[40 * SBs];  // h-blurred tmp
    __shared__ __align__(16) float bufM[36 * SMs];  // channel-summed grad magnitude

    const int tid = threadIdx.x;
    const int bx = blockIdx.x * TW;
    const int by = blockIdx.y * TH;
    // interior: tile + full halo (rows by-4..by+35, cols bx-4..bx+67) inside image
    const bool interior = (blockIdx.x >= 1 && blockIdx.x <= 62 &&
                           blockIdx.y >= 1 && blockIdx.y <= 126);

    const float g0 = gauss[0], g1 = gauss[1], g2 = gauss[2],
                g3 = gauss[3], g4 = gauss[4];

    // this thread's fixed 4-wide x 2-tall output patch
    const int ox = 4 * (tid & 15);
    const int oy = 2 * (tid >> 4);

    float gxa[8], gya[8];
    #pragma unroll
    for (int i = 0; i < 8; i++) { gxa[i] = 0.0f; gya[i] = 0.0f; }

    for (int c = 0; c < 3; c++) {
        const float* im = img + (size_t)c * (IMG_H * IMG_W);

        // ---- S1: load img tile 40 rows x 72 cols into bufA ----
        if (interior) {
            #pragma unroll
            for (int it = 0; it < 3; it++) {
                int p = tid + it * NT;
                if (p < 720) {                       // 40 rows x 18 float4
                    int r = p / 18;
                    int c4 = (p - r * 18) * 4;
                    float4 v = *(const float4*)(im + (size_t)(by - 4 + r) * IMG_W + (bx - 4) + c4);
                    *(float4*)&bufA[r * SA + c4] = v;
                }
            }
        } else {
            for (int p = tid; p < 2880; p += NT) {   // 40 x 72 scalar, zero OOB
                int r = p / 72;
                int cc = p - r * 72;
                int iy = by - 4 + r, ix = bx - 4 + cc;
                float v = 0.0f;
                if (iy >= 0 && iy < IMG_H && ix >= 0 && ix < IMG_W)
                    v = im[(size_t)iy * IMG_W + ix];
                bufA[r * SA + cc] = v;
            }
        }
        __syncthreads();

        // ---- S2: horizontal gaussian -> bufB (40 rows x 68 cols), 2x4 patches ----
        #pragma unroll
        for (int it = 0; it < 2; it++) {
            int p = tid + it * NT;
            if (p < 340) {                           // 20 row-pairs x 17 col4
                int pr = p / 17;
                int pc = p - pr * 17;
                int r0 = 2 * pr, j0 = 4 * pc;
                #pragma unroll
                for (int rr = 0; rr < 2; rr++) {
                    const float* a = &bufA[(r0 + rr) * SA + j0];
                    float4 lo = *(const float4*)a;
                    float4 hi = *(const float4*)(a + 4);
                    float t0 = g0*lo.x + g1*lo.y + g2*lo.z + g3*lo.w + g4*hi.x;
                    float t1 = g0*lo.y + g1*lo.z + g2*lo.w + g3*hi.x + g4*hi.y;
                    float t2 = g0*lo.z + g1*lo.w + g2*hi.x + g3*hi.y + g4*hi.z;
                    float t3 = g0*lo.w + g1*hi.x + g2*hi.y + g3*hi.z + g4*hi.w;
                    *(float4*)&bufB[(r0 + rr) * SBs + j0] = make_float4(t0, t1, t2, t3);
                }
            }
        }
        __syncthreads();

        // ---- S3: vertical gaussian -> blur in bufA (36 rows x 68 cols), 2x4 patches ----
        #pragma unroll
        for (int it = 0; it < 2; it++) {
            int p = tid + it * NT;
            if (p < 306) {                           // 18 row-pairs x 17 col4
                int pr = p / 17;
                int pc = p - pr * 17;
                int r0 = 2 * pr, j0 = 4 * pc;
                float4 t0 = *(const float4*)&bufB[(r0 + 0) * SBs + j0];
                float4 t1 = *(const float4*)&bufB[(r0 + 1) * SBs + j0];
                float4 t2 = *(const float4*)&bufB[(r0 + 2) * SBs + j0];
                float4 t3 = *(const float4*)&bufB[(r0 + 3) * SBs + j0];
                float4 t4 = *(const float4*)&bufB[(r0 + 4) * SBs + j0];
                float4 t5 = *(const float4*)&bufB[(r0 + 5) * SBs + j0];
                float4 b0, b1;
                b0.x = g0*t0.x + g1*t1.x + g2*t2.x + g3*t3.x + g4*t4.x;
                b0.y = g0*t0.y + g1*t1.y + g2*t2.y + g3*t3.y + g4*t4.y;
                b0.z = g0*t0.z + g1*t1.z + g2*t2.z + g3*t3.z + g4*t4.z;
                b0.w = g0*t0.w + g1*t1.w + g2*t2.w + g3*t3.w + g4*t4.w;
                b1.x = g0*t1.x + g1*t2.x + g2*t3.x + g3*t4.x + g4*t5.x;
                b1.y = g0*t1.y + g1*t2.y + g2*t3.y + g3*t4.y + g4*t5.y;
                b1.z = g0*t1.z + g1*t2.z + g2*t3.z + g3*t4.z + g4*t5.z;
                b1.w = g0*t1.w + g1*t2.w + g2*t3.w + g3*t4.w + g4*t5.w;
                if (!interior) {
                    // zero blur outside image (matches conv zero padding)
                    int iy0 = by - 2 + r0;
                    int ixb = bx - 2 + j0;
                    float* p0 = &b0.x; float* p1 = &b1.x;
                    #pragma unroll
                    for (int cc = 0; cc < 4; cc++) {
                        int ix = ixb + cc;
                        bool okx = (ix >= 0 && ix < IMG_W);
                        if (!(okx && iy0     >= 0 && iy0     < IMG_H)) p0[cc] = 0.0f;
                        if (!(okx && iy0 + 1 >= 0 && iy0 + 1 < IMG_H)) p1[cc] = 0.0f;
                    }
                }
                *(float4*)&bufA[(r0 + 0) * SA + j0] = b0;
                *(float4*)&bufA[(r0 + 1) * SA + j0] = b1;
            }
        }
        __syncthreads();

        // ---- S4: sobel magnitude -> bufM (rows 1..34, jm = magcol-1 in 0..67) ----
        #pragma unroll
        for (int it = 0; it < 2; it++) {
            int p = tid + it * NT;
            if (p < 289) {                           // 17 row-pairs x 17 col4
                int pr = p / 17;
                int pc = p - pr * 17;
                int r0 = 1 + 2 * pr;                 // mag rows r0, r0+1 in [1,34]
                int cb = 4 * pc;                     // blur col base (= magcol-1)
                float rv[4][6];
                #pragma unroll
                for (int rr = 0; rr < 4; rr++) {
                    const float* b = &bufA[(r0 - 1 + rr) * SA + cb];
                    float4 lo = *(const float4*)b;
                    float2 hi = *(const float2*)(b + 4);
                    rv[rr][0] = lo.x; rv[rr][1] = lo.y; rv[rr][2] = lo.z;
                    rv[rr][3] = lo.w; rv[rr][4] = hi.x; rv[rr][5] = hi.y;
                }
                #pragma unroll
                for (int rr = 0; rr < 2; rr++) {
                    float mv[4];
                    #pragma unroll
                    for (int cc = 0; cc < 4; cc++) {
                        float b00 = rv[rr][cc],     b01 = rv[rr][cc+1],     b02 = rv[rr][cc+2];
                        float b10 = rv[rr+1][cc],                           b12 = rv[rr+1][cc+2];
                        float b20 = rv[rr+2][cc],   b21 = rv[rr+2][cc+1],   b22 = rv[rr+2][cc+2];
                        float gxv = (b00 - b02) + 2.0f * (b10 - b12) + (b20 - b22);
                        float gyv = (b00 - b20) + 2.0f * (b01 - b21) + (b02 - b22);
                        float m = sqrtf(gxv * gxv + gyv * gyv + 1e-8f);
                        if (!interior) {
                            int iy = by - 2 + r0 + rr;
                            int ix = bx - 2 + cb + 1 + cc;
                            if (iy < 0 || iy >= IMG_H || ix < 0 || ix >= IMG_W) m = 0.0f;
                        }
                        mv[cc] = m;
                    }
                    float* dst = &bufM[(r0 + rr) * SMs + cb];
                    if (c == 0) {
                        *(float4*)dst = make_float4(mv[0], mv[1], mv[2], mv[3]);
                    } else {
                        float4 o = *(const float4*)dst;
                        *(float4*)dst = make_float4(o.x + mv[0], o.y + mv[1],
                                                    o.z + mv[2], o.w + mv[3]);
                    }
                }
            }
        }

        // ---- S4b: sobel gx/gy accumulated in registers at this thread's outputs ----
        // per output row (3x8 window) to keep the transient register set small
        #pragma unroll
        for (int rr = 0; rr < 2; rr++) {
            float rv[3][8];
            #pragma unroll
            for (int r = 0; r < 3; r++) {
                const float* b = &bufA[(oy + rr + 1 + r) * SA + ox];
                float4 lo = *(const float4*)b;
                float4 hi = *(const float4*)(b + 4);
                rv[r][0] = lo.x; rv[r][1] = lo.y; rv[r][2] = lo.z; rv[r][3] = lo.w;
                rv[r][4] = hi.x; rv[r][5] = hi.y; rv[r][6] = hi.z; rv[r][7] = hi.w;
            }
            #pragma unroll
            for (int cc = 0; cc < 4; cc++) {
                float b00 = rv[0][cc+1], b01 = rv[0][cc+2], b02 = rv[0][cc+3];
                float b10 = rv[1][cc+1],                    b12 = rv[1][cc+3];
                float b20 = rv[2][cc+1], b21 = rv[2][cc+2], b22 = rv[2][cc+3];
                gxa[rr*4+cc] += (b00 - b02) + 2.0f * (b10 - b12) + (b20 - b22);
                gya[rr*4+cc] += (b00 - b20) + 2.0f * (b01 - b21) + (b02 - b22);
            }
        }
        __syncthreads();   // mag done / bufA free for next channel
    }

    // ---- S5: orientation, NMS, threshold, write ----
    const unsigned DYP = 0x00012221u;   // nibble ip -> dy+1
    const unsigned DXP = 0x21000122u;   // nibble ip -> dx+1
    const float RAD2DEG = (float)(180.0 / 3.14159);

    #pragma unroll
    for (int rr = 0; rr < 2; rr++) {
        float ov[4];
        #pragma unroll
        for (int cc = 0; cc < 4; cc++) {
            int y = oy + rr, x = ox + cc;
            float m  = bufM[(y + 2) * SMs + (x + 1)];
            float gx = gxa[rr*4+cc];
            float gy = gya[rr*4+cc];
            float t = atan2f(gy, gx) * RAD2DEG + 180.0f;
            int k = (int)rintf(t / 45.0f);
            int ip = k & 7;
            int dy = (int)((DYP >> (ip * 4)) & 7u) - 1;
            int dx = (int)((DXP >> (ip * 4)) & 7u) - 1;
            float mp = bufM[(y + 2 + dy) * SMs + (x + 1 + dx)];
            float mn = bufM[(y + 2 - dy) * SMs + (x + 1 - dx)];
            bool is_max = fminf(m - mp, m - mn) > 0.0f;
            ov[cc] = (is_max && m >= 6.0f && m <= 50.0f) ? 1.0f : 0.0f;
        }
        *(float4*)(out + (size_t)(by + oy + rr) * IMG_W + bx + ox) =
            make_float4(ov[0], ov[1], ov[2], ov[3]);
    }
}

extern "C" void kernel_launch(void* const* d_in, const int* in_sizes, int n_in,
                              void* d_out, int out_size) {
    const float* img   = (const float*)d_in[0];  // [1,3,4096,4096]
    const float* gauss = (const float*)d_in[1];  // [5]
    float* out = (float*)d_out;                  // [1,1,4096,4096]

    dim3 grid(IMG_W / TW, IMG_H / TH);
    canny_kernel<<<grid, NT>>>(img, gauss, out);
}

// round 4
// speedup vs baseline: 1.6666x; 1.1224x over previous
#include <cuda_runtime.h>
#include <math.h>

#define IMG_W 4096
#define IMG_H 4096
#define TW 64           // output tile width
#define TH 32           // output tile height
#define NT 256

// shared strides (floats), multiples of 4 for LDS.128
#define SA  76          // bufA: img 40x72, then blur 36x68 (aliased)
#define SBs 68          // bufB: h-blurred tmp 40x68
#define SMs 72          // bufM: 34 rows (mag rows 1..34), mag col m at index m+3

__global__ __launch_bounds__(NT, 4) void canny_kernel(
    const float* __restrict__ img,
    const float* __restrict__ gauss,
    float* __restrict__ out)
{
    __shared__ __align__(16) float bufA[40 * SA];
    __shared__ __align__(16) float bufB[40 * SBs];
    __shared__ __align__(16) float bufM[34 * SMs];

    const int tid = threadIdx.x;
    const int bx = blockIdx.x * TW;
    const int by = blockIdx.y * TH;
    const bool interior = (blockIdx.x >= 1 && blockIdx.x <= 62 &&
                           blockIdx.y >= 1 && blockIdx.y <= 126);

    const float g0 = gauss[0], g1 = gauss[1], g2 = gauss[2],
                g3 = gauss[3], g4 = gauss[4];

    // this thread's 4-wide x 2-tall output patch
    const int ox = 4 * (tid & 15);
    const int oy = 2 * (tid >> 4);

    // patch mapping shared by S2/S3 (row-pairs x 17 col4)
    const int pA_r = 2 * (tid / 17), pA_j = 4 * (tid % 17);
    const int t2 = tid + NT;
    const int pB_r = 2 * (t2 / 17), pB_j = 4 * (t2 % 17);

    // ring pixel (mag coords: rows {1,34} x cols 0..65, cols {0,65} x rows 2..33)
    int mr = 1, mc = 0;
    const bool has_ring = (tid < 196);
    if (tid < 66)       { mr = 1;         mc = tid; }
    else if (tid < 132) { mr = 34;        mc = tid - 66; }
    else if (tid < 164) { mr = tid - 130; mc = 0; }
    else if (tid < 196) { mr = tid - 162; mc = 65; }

    float gxa[8], gya[8], maga[8];
    #pragma unroll
    for (int i = 0; i < 8; i++) { gxa[i] = 0.0f; gya[i] = 0.0f; maga[i] = 0.0f; }
    float ring_m = 0.0f;

    for (int c = 0; c < 3; c++) {
        const float* im = img + (size_t)c * (IMG_H * IMG_W);

        // ---- S1: load img tile 40 rows x 72 cols into bufA ----
        if (interior) {
            #pragma unroll
            for (int it = 0; it < 3; it++) {
                int p = tid + it * NT;
                if (p < 720) {                       // 40 rows x 18 float4
                    int r = p / 18;
                    int c4 = (p - r * 18) * 4;
                    float4 v = *(const float4*)(im + (size_t)(by - 4 + r) * IMG_W + (bx - 4) + c4);
                    *(float4*)&bufA[r * SA + c4] = v;
                }
            }
        } else {
            for (int p = tid; p < 2880; p += NT) {   // 40 x 72 scalar, zero OOB
                int r = p / 72;
                int cc = p - r * 72;
                int iy = by - 4 + r, ix = bx - 4 + cc;
                float v = 0.0f;
                if (iy >= 0 && iy < IMG_H && ix >= 0 && ix < IMG_W)
                    v = im[(size_t)iy * IMG_W + ix];
                bufA[r * SA + cc] = v;
            }
        }
        __syncthreads();

        // ---- S2: horizontal gaussian -> bufB (40 rows x 68 cols) ----
        {
            #pragma unroll
            for (int rr = 0; rr < 2; rr++) {
                const float* a = &bufA[(pA_r + rr) * SA + pA_j];
                float4 lo = *(const float4*)a;
                float4 hi = *(const float4*)(a + 4);
                float t0 = g0*lo.x + g1*lo.y + g2*lo.z + g3*lo.w + g4*hi.x;
                float t1 = g0*lo.y + g1*lo.z + g2*lo.w + g3*hi.x + g4*hi.y;
                float t2_ = g0*lo.z + g1*lo.w + g2*hi.x + g3*hi.y + g4*hi.z;
                float t3 = g0*lo.w + g1*hi.x + g2*hi.y + g3*hi.z + g4*hi.w;
                *(float4*)&bufB[(pA_r + rr) * SBs + pA_j] = make_float4(t0, t1, t2_, t3);
            }
            if (tid < 84) {                          // patch B: 340 total
                #pragma unroll
                for (int rr = 0; rr < 2; rr++) {
                    const float* a = &bufA[(pB_r + rr) * SA + pB_j];
                    float4 lo = *(const float4*)a;
                    float4 hi = *(const float4*)(a + 4);
                    float t0 = g0*lo.x + g1*lo.y + g2*lo.z + g3*lo.w + g4*hi.x;
                    float t1 = g0*lo.y + g1*lo.z + g2*lo.w + g3*hi.x + g4*hi.y;
                    float t2_ = g0*lo.z + g1*lo.w + g2*hi.x + g3*hi.y + g4*hi.z;
                    float t3 = g0*lo.w + g1*hi.x + g2*hi.y + g3*hi.z + g4*hi.w;
                    *(float4*)&bufB[(pB_r + rr) * SBs + pB_j] = make_float4(t0, t1, t2_, t3);
                }
            }
        }
        __syncthreads();

        // ---- S3: vertical gaussian -> blur in bufA (36 rows x 68 cols) ----
        {
            #pragma unroll
            for (int it = 0; it < 2; it++) {
                int r0 = (it == 0) ? pA_r : pB_r;
                int j0 = (it == 0) ? pA_j : pB_j;
                if (it == 1 && tid >= 50) break;     // 306 total patches
                float4 t0 = *(const float4*)&bufB[(r0 + 0) * SBs + j0];
                float4 t1 = *(const float4*)&bufB[(r0 + 1) * SBs + j0];
                float4 t2_ = *(const float4*)&bufB[(r0 + 2) * SBs + j0];
                float4 t3 = *(const float4*)&bufB[(r0 + 3) * SBs + j0];
                float4 t4 = *(const float4*)&bufB[(r0 + 4) * SBs + j0];
                float4 t5 = *(const float4*)&bufB[(r0 + 5) * SBs + j0];
                float4 b0, b1;
                b0.x = g0*t0.x + g1*t1.x + g2*t2_.x + g3*t3.x + g4*t4.x;
                b0.y = g0*t0.y + g1*t1.y + g2*t2_.y + g3*t3.y + g4*t4.y;
                b0.z = g0*t0.z + g1*t1.z + g2*t2_.z + g3*t3.z + g4*t4.z;
                b0.w = g0*t0.w + g1*t1.w + g2*t2_.w + g3*t3.w + g4*t4.w;
                b1.x = g0*t1.x + g1*t2_.x + g2*t3.x + g3*t4.x + g4*t5.x;
                b1.y = g0*t1.y + g1*t2_.y + g2*t3.y + g3*t4.y + g4*t5.y;
                b1.z = g0*t1.z + g1*t2_.z + g2*t3.z + g3*t4.z + g4*t5.z;
                b1.w = g0*t1.w + g1*t2_.w + g2*t3.w + g3*t4.w + g4*t5.w;
                if (!interior) {
                    int iy0 = by - 2 + r0;
                    int ixb = bx - 2 + j0;
                    float* p0 = &b0.x; float* p1 = &b1.x;
                    #pragma unroll
                    for (int cc = 0; cc < 4; cc++) {
                        int ix = ixb + cc;
                        bool okx = (ix >= 0 && ix < IMG_W);
                        if (!(okx && iy0     >= 0 && iy0     < IMG_H)) p0[cc] = 0.0f;
                        if (!(okx && iy0 + 1 >= 0 && iy0 + 1 < IMG_H)) p1[cc] = 0.0f;
                    }
                }
                *(float4*)&bufA[(r0 + 0) * SA + j0] = b0;
                *(float4*)&bufA[(r0 + 1) * SA + j0] = b1;
            }
        }
        __syncthreads();

        // ---- S4: merged sobel at output patch -> register accumulators ----
        {
            const float* b = &bufA[(oy + 1) * SA + ox];
            float r0[8], r1[8], r2[8], r3[8];
            {
                float4 lo, hi;
                lo = *(const float4*)(b);            hi = *(const float4*)(b + 4);
                r0[0]=lo.x; r0[1]=lo.y; r0[2]=lo.z; r0[3]=lo.w; r0[4]=hi.x; r0[5]=hi.y; r0[6]=hi.z; r0[7]=hi.w;
                lo = *(const float4*)(b + SA);       hi = *(const float4*)(b + SA + 4);
                r1[0]=lo.x; r1[1]=lo.y; r1[2]=lo.z; r1[3]=lo.w; r1[4]=hi.x; r1[5]=hi.y; r1[6]=hi.z; r1[7]=hi.w;
                lo = *(const float4*)(b + 2*SA);     hi = *(const float4*)(b + 2*SA + 4);
                r2[0]=lo.x; r2[1]=lo.y; r2[2]=lo.z; r2[3]=lo.w; r2[4]=hi.x; r2[5]=hi.y; r2[6]=hi.z; r2[7]=hi.w;
            }
            #pragma unroll
            for (int cc = 0; cc < 4; cc++) {
                float b00 = r0[cc+1], b01 = r0[cc+2], b02 = r0[cc+3];
                float b10 = r1[cc+1],                 b12 = r1[cc+3];
                float b20 = r2[cc+1], b21 = r2[cc+2], b22 = r2[cc+3];
                float gxv = (b00 - b02) + 2.0f * (b10 - b12) + (b20 - b22);
                float gyv = (b00 - b20) + 2.0f * (b01 - b21) + (b02 - b22);
                gxa[cc] += gxv;
                gya[cc] += gyv;
                maga[cc] += sqrtf(gxv * gxv + gyv * gyv + 1e-8f);
            }
            {
                float4 lo = *(const float4*)(b + 3*SA);
                float4 hi = *(const float4*)(b + 3*SA + 4);
                r3[0]=lo.x; r3[1]=lo.y; r3[2]=lo.z; r3[3]=lo.w; r3[4]=hi.x; r3[5]=hi.y; r3[6]=hi.z; r3[7]=hi.w;
            }
            #pragma unroll
            for (int cc = 0; cc < 4; cc++) {
                float b00 = r1[cc+1], b01 = r1[cc+2], b02 = r1[cc+3];
                float b10 = r2[cc+1],                 b12 = r2[cc+3];
                float b20 = r3[cc+1], b21 = r3[cc+2], b22 = r3[cc+3];
                float gxv = (b00 - b02) + 2.0f * (b10 - b12) + (b20 - b22);
                float gyv = (b00 - b20) + 2.0f * (b01 - b21) + (b02 - b22);
                gxa[4+cc] += gxv;
                gya[4+cc] += gyv;
                maga[4+cc] += sqrtf(gxv * gxv + gyv * gyv + 1e-8f);
            }
        }

        // ---- S4r: halo-ring mag pixel (register accumulated) ----
        if (has_ring) {
            const float* b = &bufA[(mr - 1) * SA + mc];
            float b00 = b[0],      b01 = b[1],          b02 = b[2];
            float b10 = b[SA],                          b12 = b[SA + 2];
            float b20 = b[2 * SA], b21 = b[2 * SA + 1], b22 = b[2 * SA + 2];
            float gxv = (b00 - b02) + 2.0f * (b10 - b12) + (b20 - b22);
            float gyv = (b00 - b20) + 2.0f * (b01 - b21) + (b02 - b22);
            float m = sqrtf(gxv * gxv + gyv * gyv + 1e-8f);
            if (!interior) {
                int iy = by - 2 + mr, ix = bx - 1 + mc;
                if (iy < 0 || iy >= IMG_H || ix < 0 || ix >= IMG_W) m = 0.0f;
            }
            ring_m += m;
        }
        __syncthreads();   // bufA free for next channel
    }

    // ---- publish mag to shared (once) ----
    #pragma unroll
    for (int rr = 0; rr < 2; rr++) {
        *(float4*)&bufM[(oy + 1 + rr) * SMs + ox + 4] =
            make_float4(maga[rr*4], maga[rr*4+1], maga[rr*4+2], maga[rr*4+3]);
    }
    if (has_ring) bufM[(mr - 1) * SMs + mc + 3] = ring_m;
    __syncthreads();

    // ---- S5: orientation, NMS, threshold, write ----
    const unsigned DYP = 0x00012221u;   // nibble ip -> dy+1
    const unsigned DXP = 0x21000122u;   // nibble ip -> dx+1
    const float RAD2DEG = (float)(180.0 / 3.14159);

    #pragma unroll
    for (int rr = 0; rr < 2; rr++) {
        float ov[4];
        #pragma unroll
        for (int cc = 0; cc < 4; cc++) {
            int y = oy + rr, x = ox + cc;
            float m  = maga[rr*4+cc];
            float t = atan2f(gya[rr*4+cc], gxa[rr*4+cc]) * RAD2DEG + 180.0f;
            int k = (int)rintf(t / 45.0f);
            int ip = k & 7;
            int dy = (int)((DYP >> (ip * 4)) & 7u) - 1;
            int dx = (int)((DXP >> (ip * 4)) & 7u) - 1;
            float mp = bufM[(y + 1 + dy) * SMs + (x + 4 + dx)];
            float mn = bufM[(y + 1 - dy) * SMs + (x + 4 - dx)];
            bool is_max = fminf(m - mp, m - mn) > 0.0f;
            ov[cc] = (is_max && m >= 6.0f && m <= 50.0f) ? 1.0f : 0.0f;
        }
        *(float4*)(out + (size_t)(by + oy + rr) * IMG_W + bx + ox) =
            make_float4(ov[0], ov[1], ov[2], ov[3]);
    }
}

extern "C" void kernel_launch(void* const* d_in, const int* in_sizes, int n_in,
                              void* d_out, int out_size) {
    const float* img   = (const float*)d_in[0];  // [1,3,4096,4096]
    const float* gauss = (const float*)d_in[1];  // [5]
    float* out = (float*)d_out;                  // [1,1,4096,4096]

    dim3 grid(IMG_W / TW, IMG_H / TH);
    canny_kernel<<<grid, NT>>>(img, gauss, out);
}

// round 5
// speedup vs baseline: 1.8795x; 1.1278x over previous
#include <cuda_runtime.h>
#include <math.h>

#define IMG_W 4096
#define IMG_H 4096
#define TW 64           // output tile width
#define TH 32           // output tile height
#define NT 256

// shared strides (floats), multiples of 4 for LDS.128
#define SA  76          // bufA: img 40x72, then blur 36x68 (aliased)
#define SBs 68          // bufB: h-blurred tmp 40x68
#define SMs 72          // bufM: 34 rows (mag rows 1..34), mag col m at index m+3

__device__ __forceinline__ float4 vblur5(float g0, float g1, float g2, float g3, float g4,
                                         float4 a, float4 b, float4 c, float4 d, float4 e)
{
    float4 o;
    o.x = g0*a.x + g1*b.x + g2*c.x + g3*d.x + g4*e.x;
    o.y = g0*a.y + g1*b.y + g2*c.y + g3*d.y + g4*e.y;
    o.z = g0*a.z + g1*b.z + g2*c.z + g3*d.z + g4*e.z;
    o.w = g0*a.w + g1*b.w + g2*c.w + g3*d.w + g4*e.w;
    return o;
}

__global__ __launch_bounds__(NT, 4) void canny_kernel(
    const float* __restrict__ img,
    const float* __restrict__ gauss,
    float* __restrict__ out)
{
    __shared__ __align__(16) float bufA[40 * SA];
    __shared__ __align__(16) float bufB[40 * SBs];
    __shared__ __align__(16) float bufM[34 * SMs];

    const int tid = threadIdx.x;
    const int bx = blockIdx.x * TW;
    const int by = blockIdx.y * TH;
    const bool interior = (blockIdx.x >= 1 && blockIdx.x <= 62 &&
                           blockIdx.y >= 1 && blockIdx.y <= 126);

    const float g0 = gauss[0], g1 = gauss[1], g2 = gauss[2],
                g3 = gauss[3], g4 = gauss[4];

    // this thread's 4-wide x 2-tall output patch
    const int ox = 4 * (tid & 15);
    const int oy = 2 * (tid >> 4);

    // ---- hoisted S2 mapping: wide patches (1 row x 8 outputs), 320 items ----
    // i -> row = 8*(i>>6)+(i&7) (8 consecutive lanes = 8 different rows ->
    // bank offsets 12*r mod 32 all distinct -> conflict-free), col4 pair p=(i>>3)&7
    const int r20 = 8 * (tid >> 6) + (tid & 7);
    const int j20 = 8 * ((tid >> 3) & 7);
    const int i1  = tid + 256;                    // valid for tid < 64
    const int r21 = 8 * (i1 >> 6) + (i1 & 7);
    const int j21 = 8 * ((i1 >> 3) & 7);
    const bool s2b = (tid < 64);
    // narrow column (col4 16, cols 64..67), rows 0..39 -> tid 192..231
    const bool s2n = (tid >= 192 && tid < 232);
    const int rn = tid - 192;

    // ---- hoisted S3 mapping: 4-row x 1-col4 patches, 153 items ----
    const bool s3ok = (tid < 153);
    const int r3 = 4 * (tid / 17);                // 0..32
    const int j3 = 4 * (tid % 17);                // 0..64

    // ring pixel (mag coords: rows {1,34} x cols 0..65, cols {0,65} x rows 2..33)
    int mr = 1, mc = 0;
    const bool has_ring = (tid < 196);
    if (tid < 66)       { mr = 1;         mc = tid; }
    else if (tid < 132) { mr = 34;        mc = tid - 66; }
    else if (tid < 164) { mr = tid - 130; mc = 0; }
    else if (tid < 196) { mr = tid - 162; mc = 65; }

    float gxa[8], gya[8], maga[8];
    #pragma unroll
    for (int i = 0; i < 8; i++) { gxa[i] = 0.0f; gya[i] = 0.0f; maga[i] = 0.0f; }
    float ring_m = 0.0f;

    for (int c = 0; c < 3; c++) {
        const float* im = img + (size_t)c * (IMG_H * IMG_W);

        // ---- S1: load img tile 40 rows x 72 cols into bufA ----
        if (interior) {
            #pragma unroll
            for (int it = 0; it < 3; it++) {
                int p = tid + it * NT;
                if (p < 720) {                       // 40 rows x 18 float4
                    int r = p / 18;
                    int c4 = (p - r * 18) * 4;
                    float4 v = *(const float4*)(im + (size_t)(by - 4 + r) * IMG_W + (bx - 4) + c4);
                    *(float4*)&bufA[r * SA + c4] = v;
                }
            }
        } else {
            for (int p = tid; p < 2880; p += NT) {   // 40 x 72 scalar, zero OOB
                int r = p / 72;
                int cc = p - r * 72;
                int iy = by - 4 + r, ix = bx - 4 + cc;
                float v = 0.0f;
                if (iy >= 0 && iy < IMG_H && ix >= 0 && ix < IMG_W)
                    v = im[(size_t)iy * IMG_W + ix];
                bufA[r * SA + cc] = v;
            }
        }
        __syncthreads();

        // ---- S2: horizontal gaussian -> bufB (40 rows x 68 cols) ----
        {
            // wide patch 0 (all threads)
            {
                const float* a = &bufA[r20 * SA + j20];
                float4 v0 = *(const float4*)a;
                float4 v1 = *(const float4*)(a + 4);
                float4 v2 = *(const float4*)(a + 8);
                float w0=v0.x,w1=v0.y,w2=v0.z,w3=v0.w,w4=v1.x,w5=v1.y,w6=v1.z,w7=v1.w,
                      w8=v2.x,w9=v2.y,w10=v2.z,w11=v2.w;
                float4 o0, o1;
                o0.x = g0*w0 + g1*w1 + g2*w2 + g3*w3 + g4*w4;
                o0.y = g0*w1 + g1*w2 + g2*w3 + g3*w4 + g4*w5;
                o0.z = g0*w2 + g1*w3 + g2*w4 + g3*w5 + g4*w6;
                o0.w = g0*w3 + g1*w4 + g2*w5 + g3*w6 + g4*w7;
                o1.x = g0*w4 + g1*w5 + g2*w6 + g3*w7 + g4*w8;
                o1.y = g0*w5 + g1*w6 + g2*w7 + g3*w8 + g4*w9;
                o1.z = g0*w6 + g1*w7 + g2*w8 + g3*w9 + g4*w10;
                o1.w = g0*w7 + g1*w8 + g2*w9 + g3*w10 + g4*w11;
                *(float4*)&bufB[r20 * SBs + j20]     = o0;
                *(float4*)&bufB[r20 * SBs + j20 + 4] = o1;
            }
            // wide patch 1 (tid < 64)
            if (s2b) {
                const float* a = &bufA[r21 * SA + j21];
                float4 v0 = *(const float4*)a;
                float4 v1 = *(const float4*)(a + 4);
                float4 v2 = *(const float4*)(a + 8);
                float w0=v0.x,w1=v0.y,w2=v0.z,w3=v0.w,w4=v1.x,w5=v1.y,w6=v1.z,w7=v1.w,
                      w8=v2.x,w9=v2.y,w10=v2.z,w11=v2.w;
                float4 o0, o1;
                o0.x = g0*w0 + g1*w1 + g2*w2 + g3*w3 + g4*w4;
                o0.y = g0*w1 + g1*w2 + g2*w3 + g3*w4 + g4*w5;
                o0.z = g0*w2 + g1*w3 + g2*w4 + g3*w5 + g4*w6;
                o0.w = g0*w3 + g1*w4 + g2*w5 + g3*w6 + g4*w7;
                o1.x = g0*w4 + g1*w5 + g2*w6 + g3*w7 + g4*w8;
                o1.y = g0*w5 + g1*w6 + g2*w7 + g3*w8 + g4*w9;
                o1.z = g0*w6 + g1*w7 + g2*w8 + g3*w9 + g4*w10;
                o1.w = g0*w7 + g1*w8 + g2*w9 + g3*w10 + g4*w11;
                *(float4*)&bufB[r21 * SBs + j21]     = o0;
                *(float4*)&bufB[r21 * SBs + j21 + 4] = o1;
            }
            // narrow column (cols 64..67) rows 0..39 (tid 192..231)
            if (s2n) {
                const float* a = &bufA[rn * SA + 64];
                float4 v0 = *(const float4*)a;
                float4 v1 = *(const float4*)(a + 4);
                float4 o0;
                o0.x = g0*v0.x + g1*v0.y + g2*v0.z + g3*v0.w + g4*v1.x;
                o0.y = g0*v0.y + g1*v0.z + g2*v0.w + g3*v1.x + g4*v1.y;
                o0.z = g0*v0.z + g1*v0.w + g2*v1.x + g3*v1.y + g4*v1.z;
                o0.w = g0*v0.w + g1*v1.x + g2*v1.y + g3*v1.z + g4*v1.w;
                *(float4*)&bufB[rn * SBs + 64] = o0;
            }
        }
        __syncthreads();

        // ---- S3: vertical gaussian -> blur in bufA (36 rows x 68 cols), 4-row patch ----
        if (s3ok) {
            const float* bcol = &bufB[r3 * SBs + j3];
            float* acol = &bufA[r3 * SA + j3];
            float4 t0 = *(const float4*)(bcol);
            float4 t1 = *(const float4*)(bcol + 1 * SBs);
            float4 t2 = *(const float4*)(bcol + 2 * SBs);
            float4 t3 = *(const float4*)(bcol + 3 * SBs);
            float4 t4 = *(const float4*)(bcol + 4 * SBs);
            #pragma unroll
            for (int k = 0; k < 4; k++) {
                float4 o = vblur5(g0, g1, g2, g3, g4, t0, t1, t2, t3, t4);
                if (!interior) {
                    int iy = by - 2 + r3 + k;
                    int ixb = bx - 2 + j3;
                    float* po = &o.x;
                    #pragma unroll
                    for (int cc = 0; cc < 4; cc++) {
                        int ix = ixb + cc;
                        if (!(ix >= 0 && ix < IMG_W && iy >= 0 && iy < IMG_H)) po[cc] = 0.0f;
                    }
                }
                *(float4*)(acol + k * SA) = o;
                if (k < 3) {
                    t0 = t1; t1 = t2; t2 = t3; t3 = t4;
                    t4 = *(const float4*)(bcol + (5 + k) * SBs);
                }
            }
        }
        __syncthreads();

        // ---- S4: merged sobel at output patch -> register accumulators ----
        {
            const float* b = &bufA[(oy + 1) * SA + ox];
            float r0[8], r1[8], r2[8], r3v[8];
            {
                float4 lo, hi;
                lo = *(const float4*)(b);            hi = *(const float4*)(b + 4);
                r0[0]=lo.x; r0[1]=lo.y; r0[2]=lo.z; r0[3]=lo.w; r0[4]=hi.x; r0[5]=hi.y; r0[6]=hi.z; r0[7]=hi.w;
                lo = *(const float4*)(b + SA);       hi = *(const float4*)(b + SA + 4);
                r1[0]=lo.x; r1[1]=lo.y; r1[2]=lo.z; r1[3]=lo.w; r1[4]=hi.x; r1[5]=hi.y; r1[6]=hi.z; r1[7]=hi.w;
                lo = *(const float4*)(b + 2*SA);     hi = *(const float4*)(b + 2*SA + 4);
                r2[0]=lo.x; r2[1]=lo.y; r2[2]=lo.z; r2[3]=lo.w; r2[4]=hi.x; r2[5]=hi.y; r2[6]=hi.z; r2[7]=hi.w;
            }
            #pragma unroll
            for (int cc = 0; cc < 4; cc++) {
                float b00 = r0[cc+1], b01 = r0[cc+2], b02 = r0[cc+3];
                float b10 = r1[cc+1],                 b12 = r1[cc+3];
                float b20 = r2[cc+1], b21 = r2[cc+2], b22 = r2[cc+3];
                float gxv = (b00 - b02) + 2.0f * (b10 - b12) + (b20 - b22);
                float gyv = (b00 - b20) + 2.0f * (b01 - b21) + (b02 - b22);
                gxa[cc] += gxv;
                gya[cc] += gyv;
                maga[cc] += sqrtf(gxv * gxv + gyv * gyv + 1e-8f);
            }
            {
                float4 lo = *(const float4*)(b + 3*SA);
                float4 hi = *(const float4*)(b + 3*SA + 4);
                r3v[0]=lo.x; r3v[1]=lo.y; r3v[2]=lo.z; r3v[3]=lo.w; r3v[4]=hi.x; r3v[5]=hi.y; r3v[6]=hi.z; r3v[7]=hi.w;
            }
            #pragma unroll
            for (int cc = 0; cc < 4; cc++) {
                float b00 = r1[cc+1], b01 = r1[cc+2], b02 = r1[cc+3];
                float b10 = r2[cc+1],                 b12 = r2[cc+3];
                float b20 = r3v[cc+1], b21 = r3v[cc+2], b22 = r3v[cc+3];
                float gxv = (b00 - b02) + 2.0f * (b10 - b12) + (b20 - b22);
                float gyv = (b00 - b20) + 2.0f * (b01 - b21) + (b02 - b22);
                gxa[4+cc] += gxv;
                gya[4+cc] += gyv;
                maga[4+cc] += sqrtf(gxv * gxv + gyv * gyv + 1e-8f);
            }
        }

        // ---- S4r: halo-ring mag pixel (register accumulated) ----
        if (has_ring) {
            const float* b = &bufA[(mr - 1) * SA + mc];
            float b00 = b[0],      b01 = b[1],          b02 = b[2];
            float b10 = b[SA],                          b12 = b[SA + 2];
            float b20 = b[2 * SA], b21 = b[2 * SA + 1], b22 = b[2 * SA + 2];
            float gxv = (b00 - b02) + 2.0f * (b10 - b12) + (b20 - b22);
            float gyv = (b00 - b20) + 2.0f * (b01 - b21) + (b02 - b22);
            float m = sqrtf(gxv * gxv + gyv * gyv + 1e-8f);
            if (!interior) {
                int iy = by - 2 + mr, ix = bx - 1 + mc;
                if (iy < 0 || iy >= IMG_H || ix < 0 || ix >= IMG_W) m = 0.0f;
            }
            ring_m += m;
        }
        __syncthreads();   // bufA free for next channel
    }

    // ---- publish mag to shared (once) ----
    #pragma unroll
    for (int rr = 0; rr < 2; rr++) {
        *(float4*)&bufM[(oy + 1 + rr) * SMs + ox + 4] =
            make_float4(maga[rr*4], maga[rr*4+1], maga[rr*4+2], maga[rr*4+3]);
    }
    if (has_ring) bufM[(mr - 1) * SMs + mc + 3] = ring_m;
    __syncthreads();

    // ---- S5: orientation, NMS, threshold, write ----
    const unsigned DYP = 0x00012221u;   // nibble ip -> dy+1
    const unsigned DXP = 0x21000122u;   // nibble ip -> dx+1
    const float RAD2DEG = (float)(180.0 / 3.14159);

    #pragma unroll
    for (int rr = 0; rr < 2; rr++) {
        float ov[4];
        #pragma unroll
        for (int cc = 0; cc < 4; cc++) {
            int y = oy + rr, x = ox + cc;
            float m  = maga[rr*4+cc];
            float t = atan2f(gya[rr*4+cc], gxa[rr*4+cc]) * RAD2DEG + 180.0f;
            int k = (int)rintf(t / 45.0f);
            int ip = k & 7;
            int dy = (int)((DYP >> (ip * 4)) & 7u) - 1;
            int dx = (int)((DXP >> (ip * 4)) & 7u) - 1;
            float mp = bufM[(y + 1 + dy) * SMs + (x + 4 + dx)];
            float mn = bufM[(y + 1 - dy) * SMs + (x + 4 - dx)];
            bool is_max = fminf(m - mp, m - mn) > 0.0f;
            ov[cc] = (is_max && m >= 6.0f && m <= 50.0f) ? 1.0f : 0.0f;
        }
        *(float4*)(out + (size_t)(by + oy + rr) * IMG_W + bx + ox) =
            make_float4(ov[0], ov[1], ov[2], ov[3]);
    }
}

extern "C" void kernel_launch(void* const* d_in, const int* in_sizes, int n_in,
                              void* d_out, int out_size) {
    const float* img   = (const float*)d_in[0];  // [1,3,4096,4096]
    const float* gauss = (const float*)d_in[1];  // [5]
    float* out = (float*)d_out;                  // [1,1,4096,4096]

    dim3 grid(IMG_W / TW, IMG_H / TH);
    canny_kernel<<<grid, NT>>>(img, gauss, out);
}